// round 8
// baseline (speedup 1.0000x reference)
#include <cuda_runtime.h>
#include <cstddef>
#include <cstdint>

// FISM scoring: B=16384 rows, K=50 neighbors (contiguous slice of I_U),
// NNEG=20, D=128. Fused warp-per-row kernel, R7 (resubmit — R7 bench was an
// infra failure, kernel never ran):
//  - __launch_bounds__(256,6): 48 warps/SM target (42-reg cap); epilogue
//    loads (b_u/b_i) deferred + item indices in smem to slim the live set.
//  - s_items[wid][21] kills the per-iteration shfl address dependency in
//    the dot loop -> Q loads front-batch across the unroll.
//  - float4 gathers with L2 evict_last policy; butterfly reductions;
//    coalesced 20-wide r_neg store.

#define FB    16384
#define FK    50
#define FNNEG 20
#define FD    128
#define WPB   8                      // warps (rows) per 256-thread block

// float4 gather with L2 evict_last cache hint
__device__ __forceinline__ float4 ldg_el4(const float4* p) {
    float4 v;
    asm("{\n\t"
        ".reg .b64 pol;\n\t"
        "createpolicy.fractional.L2::evict_last.b64 pol, 1.0;\n\t"
        "ld.global.nc.L2::cache_hint.v4.f32 {%0,%1,%2,%3}, [%4], pol;\n\t"
        "}"
        : "=f"(v.x), "=f"(v.y), "=f"(v.z), "=f"(v.w) : "l"(p));
    return v;
}

template<bool VEC>
__global__ __launch_bounds__(256, 6) void fism_fused(
    const int*   __restrict__ I,
    const int*   __restrict__ U,
    const int*   __restrict__ I_neg,
    const int*   __restrict__ I_U,
    const int*   __restrict__ N_U,
    const int*   __restrict__ I_in,
    const float* __restrict__ P,
    const float* __restrict__ Q,
    const float* __restrict__ b_u,
    const float* __restrict__ b_i,
    float*       __restrict__ out)
{
    const int wid  = threadIdx.x >> 5;
    const int lane = threadIdx.x & 31;
    const int b    = blockIdx.x * WPB + wid;     // FB = 2048*8 exact

    __shared__ int s_idx[WPB][FK];
    __shared__ int s_items[WPB][1 + FNNEG];      // [0]=I[b], [1..20]=I_neg row

    {
        const int* src = I_U + (size_t)b * FK;
        s_idx[wid][lane] = src[lane];
        if (lane < FK - 32) s_idx[wid][32 + lane] = src[32 + lane];
        if (lane < FNNEG)
            s_items[wid][1 + lane] = __ldg(&I_neg[(size_t)b * FNNEG + lane]);
        if (lane == 0) s_items[wid][0] = __ldg(&I[b]);
    }
    __syncwarp();

    const int   i_pos = s_items[wid][0];
    const float ind   = (float)__ldg(&I_in[b]);
    const float n_u   = (float)__ldg(&N_U[b]);

    // ---- neighbor gather + sum ------------------------------------------
    float a0 = 0.f, a1 = 0.f, a2 = 0.f, a3 = 0.f;
    #pragma unroll
    for (int k = 0; k < FK; k++) {
        const float* row = P + (size_t)s_idx[wid][k] * FD;
        if (VEC) {
            const float4 v = ldg_el4(reinterpret_cast<const float4*>(row) + lane);
            a0 += v.x; a1 += v.y; a2 += v.z; a3 += v.w;
        } else {
            a0 += __ldg(&row[lane]);
            a1 += __ldg(&row[lane + 32]);
            a2 += __ldg(&row[lane + 64]);
            a3 += __ldg(&row[lane + 96]);
        }
    }
    {   // exclude self if present
        const float* row = P + (size_t)i_pos * FD;
        if (VEC) {
            const float4 v = ldg_el4(reinterpret_cast<const float4*>(row) + lane);
            a0 -= v.x * ind; a1 -= v.y * ind; a2 -= v.z * ind; a3 -= v.w * ind;
        } else {
            a0 -= __ldg(&row[lane])      * ind;
            a1 -= __ldg(&row[lane + 32]) * ind;
            a2 -= __ldg(&row[lane + 64]) * ind;
            a3 -= __ldg(&row[lane + 96]) * ind;
        }
    }

    const float inv = 1.0f / fmaxf(n_u - ind, 1.0f);   // ALPHA = 1
    const float p0 = a0 * inv, p1 = a1 * inv, p2 = a2 * inv, p3 = a3 * inv;

    // ---- 21 dot products; lane t-1 keeps item t's score ------------------
    float my_neg = 0.0f;   // lane t (t<20): dot for r_neg[b][t]
    float r_pos  = 0.0f;

    #pragma unroll
    for (int t = 0; t < 1 + FNNEG; t++) {
        const int item = s_items[wid][t];          // LDS broadcast, no shfl dep
        const float* qr = Q + (size_t)item * FD;
        float d;
        if (VEC) {
            const float4 v = ldg_el4(reinterpret_cast<const float4*>(qr) + lane);
            d = p0 * v.x + p1 * v.y + p2 * v.z + p3 * v.w;
        } else {
            d = p0 * __ldg(&qr[lane])
              + p1 * __ldg(&qr[lane + 32])
              + p2 * __ldg(&qr[lane + 64])
              + p3 * __ldg(&qr[lane + 96]);
        }
        #pragma unroll
        for (int off = 16; off > 0; off >>= 1)
            d += __shfl_xor_sync(0xffffffffu, d, off);   // result in all lanes
        if (t == 0)               r_pos  = d;
        else if (lane == t - 1)   my_neg = d;
    }

    // ---- epilogue: biases loaded late (frees regs during gather) ---------
    const float bu = __ldg(&b_u[__ldg(&U[b])]);
    if (lane < FNNEG) {
        const float bi_n = __ldg(&b_i[s_items[wid][1 + lane]]);
        out[FB + (size_t)b * FNNEG + lane] = bu + bi_n + my_neg;
    }
    if (lane == 0)
        out[b] = bu + __ldg(&b_i[i_pos]) + r_pos;
}

extern "C" void kernel_launch(void* const* d_in, const int* in_sizes, int n_in,
                              void* d_out, int out_size)
{
    const int*   I     = (const int*)  d_in[0];
    const int*   U     = (const int*)  d_in[1];
    const int*   I_neg = (const int*)  d_in[2];
    const int*   I_U   = (const int*)  d_in[3];
    const int*   N_U   = (const int*)  d_in[4];
    const int*   I_in  = (const int*)  d_in[5];
    const float* P     = (const float*)d_in[6];
    const float* Q     = (const float*)d_in[7];
    const float* b_u   = (const float*)d_in[8];
    const float* b_i   = (const float*)d_in[9];
    float* out = (float*)d_out;

    const bool aligned = (((uintptr_t)P & 15u) == 0) && (((uintptr_t)Q & 15u) == 0);
    dim3 grid(FB / WPB), block(32 * WPB);

    if (aligned)
        fism_fused<true ><<<grid, block>>>(I, U, I_neg, I_U, N_U, I_in, P, Q, b_u, b_i, out);
    else
        fism_fused<false><<<grid, block>>>(I, U, I_neg, I_U, N_U, I_in, P, Q, b_u, b_i, out);
}

// round 11
// speedup vs baseline: 1.0373x; 1.0373x over previous
#include <cuda_runtime.h>
#include <cstddef>
#include <cstdint>

// FISM scoring: B=16384 rows, K=50 neighbors (contiguous slice of I_U),
// NNEG=20, D=128. Fused warp-per-row kernel.
// R11 = third submit of the R9 kernel (R9/R10 both died to broker
// GPUAcquisitionTimeout — kernel never ran):
// R6 winner (launch_bounds(256,5), 48 regs, biases hoisted) + ONE change:
// item indices for the 21-dot loop staged in smem (LDS broadcast) instead of
// shfl-broadcast registers -> Q-row addresses have no cross-iteration
// dependency, letting ptxas front-batch the Q LDG.128s (higher phase-2 MLP).
// Lesson from R8: do NOT cap regs below ~48 — per-warp MLP loss beats the
// occupancy gain.

#define FB    16384
#define FK    50
#define FNNEG 20
#define FD    128
#define WPB   8                      // warps (rows) per 256-thread block

// float4 gather with L2 evict_last cache hint
__device__ __forceinline__ float4 ldg_el4(const float4* p) {
    float4 v;
    asm("{\n\t"
        ".reg .b64 pol;\n\t"
        "createpolicy.fractional.L2::evict_last.b64 pol, 1.0;\n\t"
        "ld.global.nc.L2::cache_hint.v4.f32 {%0,%1,%2,%3}, [%4], pol;\n\t"
        "}"
        : "=f"(v.x), "=f"(v.y), "=f"(v.z), "=f"(v.w) : "l"(p));
    return v;
}

template<bool VEC>
__global__ __launch_bounds__(256, 5) void fism_fused(
    const int*   __restrict__ I,
    const int*   __restrict__ U,
    const int*   __restrict__ I_neg,
    const int*   __restrict__ I_U,
    const int*   __restrict__ N_U,
    const int*   __restrict__ I_in,
    const float* __restrict__ P,
    const float* __restrict__ Q,
    const float* __restrict__ b_u,
    const float* __restrict__ b_i,
    float*       __restrict__ out)
{
    const int wid  = threadIdx.x >> 5;
    const int lane = threadIdx.x & 31;
    const int b    = blockIdx.x * WPB + wid;     // FB = 2048*8 exact

    __shared__ int s_idx[WPB][FK];
    __shared__ int s_items[WPB][1 + FNNEG];      // [0]=I[b], [1..20]=I_neg row

    {
        const int* src = I_U + (size_t)b * FK;
        s_idx[wid][lane] = src[lane];
        if (lane < FK - 32) s_idx[wid][32 + lane] = src[32 + lane];
        if (lane < FNNEG)
            s_items[wid][1 + lane] = __ldg(&I_neg[(size_t)b * FNNEG + lane]);
        if (lane == 0) s_items[wid][0] = __ldg(&I[b]);
    }
    __syncwarp();

    // hoisted scalars (R6 layout — hides their latency under the gather)
    const int   i_pos = s_items[wid][0];
    const float ind   = (float)__ldg(&I_in[b]);
    const float n_u   = (float)__ldg(&N_U[b]);
    const float bu    = __ldg(&b_u[__ldg(&U[b])]);
    const float bi_n  = (lane < FNNEG)
                      ? __ldg(&b_i[s_items[wid][1 + lane]]) : 0.0f;
    const float bi_p  = __ldg(&b_i[i_pos]);

    // ---- neighbor gather + sum ------------------------------------------
    float a0 = 0.f, a1 = 0.f, a2 = 0.f, a3 = 0.f;
    #pragma unroll
    for (int k = 0; k < FK; k++) {
        const float* row = P + (size_t)s_idx[wid][k] * FD;
        if (VEC) {
            const float4 v = ldg_el4(reinterpret_cast<const float4*>(row) + lane);
            a0 += v.x; a1 += v.y; a2 += v.z; a3 += v.w;
        } else {
            a0 += __ldg(&row[lane]);
            a1 += __ldg(&row[lane + 32]);
            a2 += __ldg(&row[lane + 64]);
            a3 += __ldg(&row[lane + 96]);
        }
    }
    {   // exclude self if present
        const float* row = P + (size_t)i_pos * FD;
        if (VEC) {
            const float4 v = ldg_el4(reinterpret_cast<const float4*>(row) + lane);
            a0 -= v.x * ind; a1 -= v.y * ind; a2 -= v.z * ind; a3 -= v.w * ind;
        } else {
            a0 -= __ldg(&row[lane])      * ind;
            a1 -= __ldg(&row[lane + 32]) * ind;
            a2 -= __ldg(&row[lane + 64]) * ind;
            a3 -= __ldg(&row[lane + 96]) * ind;
        }
    }

    const float inv = 1.0f / fmaxf(n_u - ind, 1.0f);   // ALPHA = 1
    const float p0 = a0 * inv, p1 = a1 * inv, p2 = a2 * inv, p3 = a3 * inv;

    // ---- 21 dot products; lane t-1 keeps item t's score ------------------
    float my_neg = 0.0f;   // lane t (t<20): dot for r_neg[b][t]
    float r_pos  = 0.0f;

    #pragma unroll
    for (int t = 0; t < 1 + FNNEG; t++) {
        const int item = s_items[wid][t];          // LDS broadcast, no shfl dep
        const float* qr = Q + (size_t)item * FD;
        float d;
        if (VEC) {
            const float4 v = ldg_el4(reinterpret_cast<const float4*>(qr) + lane);
            d = p0 * v.x + p1 * v.y + p2 * v.z + p3 * v.w;
        } else {
            d = p0 * __ldg(&qr[lane])
              + p1 * __ldg(&qr[lane + 32])
              + p2 * __ldg(&qr[lane + 64])
              + p3 * __ldg(&qr[lane + 96]);
        }
        #pragma unroll
        for (int off = 16; off > 0; off >>= 1)
            d += __shfl_xor_sync(0xffffffffu, d, off);   // result in all lanes
        if (t == 0)               r_pos  = d;
        else if (lane == t - 1)   my_neg = d;
    }

    // coalesced epilogue: one 20-wide store + one scalar
    if (lane < FNNEG)
        out[FB + (size_t)b * FNNEG + lane] = bu + bi_n + my_neg;
    if (lane == 0)
        out[b] = bu + bi_p + r_pos;
}

extern "C" void kernel_launch(void* const* d_in, const int* in_sizes, int n_in,
                              void* d_out, int out_size)
{
    const int*   I     = (const int*)  d_in[0];
    const int*   U     = (const int*)  d_in[1];
    const int*   I_neg = (const int*)  d_in[2];
    const int*   I_U   = (const int*)  d_in[3];
    const int*   N_U   = (const int*)  d_in[4];
    const int*   I_in  = (const int*)  d_in[5];
    const float* P     = (const float*)d_in[6];
    const float* Q     = (const float*)d_in[7];
    const float* b_u   = (const float*)d_in[8];
    const float* b_i   = (const float*)d_in[9];
    float* out = (float*)d_out;

    const bool aligned = (((uintptr_t)P & 15u) == 0) && (((uintptr_t)Q & 15u) == 0);
    dim3 grid(FB / WPB), block(32 * WPB);

    if (aligned)
        fism_fused<true ><<<grid, block>>>(I, U, I_neg, I_U, N_U, I_in, P, Q, b_u, b_i, out);
    else
        fism_fused<false><<<grid, block>>>(I, U, I_neg, I_U, N_U, I_in, P, Q, b_u, b_i, out);
}

// round 12
// speedup vs baseline: 1.1243x; 1.0838x over previous
#include <cuda_runtime.h>
#include <cstddef>
#include <cstdint>

// FISM scoring: B=16384 rows, K=50 neighbors (contiguous slice of I_U),
// NNEG=20, D=128. Fused warp-per-row kernel.
// R12 = R6 winner (41.5us: launch_bounds(256,5)/48regs, shfl item broadcast,
// hoisted biases) + ONE change: smem-transpose reduction for the 21 dots.
// Each iteration writes its per-lane partial to s_part[w][t][lane] (padded,
// conflict-free) instead of a 5-deep dependent shfl chain; lanes 0..20 then
// each sum one row. Kills ~2700 cyc of serial shfl latency per warp and lets
// all 21 Q-row LDG.128s overlap.
// Lessons: R8 = don't cap regs below ~48; R11 = don't replace independent
// shfl broadcasts with LDS.

#define FB    16384
#define FK    50
#define FNNEG 20
#define FD    128
#define WPB   8                      // warps (rows) per 256-thread block
#define NITEM (1 + FNNEG)            // 21

// float4 gather with L2 evict_last cache hint
__device__ __forceinline__ float4 ldg_el4(const float4* p) {
    float4 v;
    asm("{\n\t"
        ".reg .b64 pol;\n\t"
        "createpolicy.fractional.L2::evict_last.b64 pol, 1.0;\n\t"
        "ld.global.nc.L2::cache_hint.v4.f32 {%0,%1,%2,%3}, [%4], pol;\n\t"
        "}"
        : "=f"(v.x), "=f"(v.y), "=f"(v.z), "=f"(v.w) : "l"(p));
    return v;
}

template<bool VEC>
__global__ __launch_bounds__(256, 5) void fism_fused(
    const int*   __restrict__ I,
    const int*   __restrict__ U,
    const int*   __restrict__ I_neg,
    const int*   __restrict__ I_U,
    const int*   __restrict__ N_U,
    const int*   __restrict__ I_in,
    const float* __restrict__ P,
    const float* __restrict__ Q,
    const float* __restrict__ b_u,
    const float* __restrict__ b_i,
    float*       __restrict__ out)
{
    const int wid  = threadIdx.x >> 5;
    const int lane = threadIdx.x & 31;
    const int b    = blockIdx.x * WPB + wid;     // FB = 2048*8 exact

    __shared__ int   s_idx[WPB][FK];
    __shared__ float s_part[WPB][NITEM][33];     // padded: bank=(t+lane)%32

    {
        const int* src = I_U + (size_t)b * FK;
        s_idx[wid][lane] = src[lane];
        if (lane < FK - 32) s_idx[wid][32 + lane] = src[32 + lane];
    }
    __syncwarp();

    // hoisted scalars (hide their latency under the gather)
    const int   i_pos = __ldg(&I[b]);
    const float ind   = (float)__ldg(&I_in[b]);
    const float n_u   = (float)__ldg(&N_U[b]);
    const float bu    = __ldg(&b_u[__ldg(&U[b])]);
    const int   negi  = (lane < FNNEG) ? __ldg(&I_neg[(size_t)b * FNNEG + lane]) : 0;
    const float bi_n  = (lane < FNNEG) ? __ldg(&b_i[negi]) : 0.0f;
    const float bi_p  = __ldg(&b_i[i_pos]);

    // ---- neighbor gather + sum ------------------------------------------
    float a0 = 0.f, a1 = 0.f, a2 = 0.f, a3 = 0.f;
    #pragma unroll
    for (int k = 0; k < FK; k++) {
        const float* row = P + (size_t)s_idx[wid][k] * FD;
        if (VEC) {
            const float4 v = ldg_el4(reinterpret_cast<const float4*>(row) + lane);
            a0 += v.x; a1 += v.y; a2 += v.z; a3 += v.w;
        } else {
            a0 += __ldg(&row[lane]);
            a1 += __ldg(&row[lane + 32]);
            a2 += __ldg(&row[lane + 64]);
            a3 += __ldg(&row[lane + 96]);
        }
    }
    {   // exclude self if present
        const float* row = P + (size_t)i_pos * FD;
        if (VEC) {
            const float4 v = ldg_el4(reinterpret_cast<const float4*>(row) + lane);
            a0 -= v.x * ind; a1 -= v.y * ind; a2 -= v.z * ind; a3 -= v.w * ind;
        } else {
            a0 -= __ldg(&row[lane])      * ind;
            a1 -= __ldg(&row[lane + 32]) * ind;
            a2 -= __ldg(&row[lane + 64]) * ind;
            a3 -= __ldg(&row[lane + 96]) * ind;
        }
    }

    const float inv = 1.0f / fmaxf(n_u - ind, 1.0f);   // ALPHA = 1
    const float p0 = a0 * inv, p1 = a1 * inv, p2 = a2 * inv, p3 = a3 * inv;

    // ---- 21 dot partials: independent load->FFMA->STS, no reduce chains --
    #pragma unroll
    for (int t = 0; t < NITEM; t++) {
        const int item = (t == 0) ? i_pos : __shfl_sync(0xffffffffu, negi, t - 1);
        const float* qr = Q + (size_t)item * FD;
        float d;
        if (VEC) {
            const float4 v = ldg_el4(reinterpret_cast<const float4*>(qr) + lane);
            d = p0 * v.x + p1 * v.y + p2 * v.z + p3 * v.w;
        } else {
            d = p0 * __ldg(&qr[lane])
              + p1 * __ldg(&qr[lane + 32])
              + p2 * __ldg(&qr[lane + 64])
              + p3 * __ldg(&qr[lane + 96]);
        }
        s_part[wid][t][lane] = d;
    }
    __syncwarp();

    // ---- transpose reduce: lane t sums item t's 32 partials --------------
    // lane 0 -> r (positive), lanes 1..20 -> r_neg[lane-1]
    const float bias_up = __shfl_up_sync(0xffffffffu, bi_n, 1); // lane t: b_i of item t
    if (lane < NITEM) {
        float acc = 0.0f;
        #pragma unroll
        for (int i = 0; i < 32; i++)
            acc += s_part[wid][lane][i];       // bank (lane+i)%32: conflict-free
        if (lane == 0)
            out[b] = bu + bi_p + acc;
        else
            out[FB + (size_t)b * FNNEG + (lane - 1)] = bu + bias_up + acc;
    }
}

extern "C" void kernel_launch(void* const* d_in, const int* in_sizes, int n_in,
                              void* d_out, int out_size)
{
    const int*   I     = (const int*)  d_in[0];
    const int*   U     = (const int*)  d_in[1];
    const int*   I_neg = (const int*)  d_in[2];
    const int*   I_U   = (const int*)  d_in[3];
    const int*   N_U   = (const int*)  d_in[4];
    const int*   I_in  = (const int*)  d_in[5];
    const float* P     = (const float*)d_in[6];
    const float* Q     = (const float*)d_in[7];
    const float* b_u   = (const float*)d_in[8];
    const float* b_i   = (const float*)d_in[9];
    float* out = (float*)d_out;

    const bool aligned = (((uintptr_t)P & 15u) == 0) && (((uintptr_t)Q & 15u) == 0);
    dim3 grid(FB / WPB), block(32 * WPB);

    if (aligned)
        fism_fused<true ><<<grid, block>>>(I, U, I_neg, I_U, N_U, I_in, P, Q, b_u, b_i, out);
    else
        fism_fused<false><<<grid, block>>>(I, U, I_neg, I_U, N_U, I_in, P, Q, b_u, b_i, out);
}